// round 7
// baseline (speedup 1.0000x reference)
#include <cuda_runtime.h>
#include <math.h>

#define Bz   128
#define Hh   512
#define G4   2048
#define Tt   256
#define INZ  64
#define OUTL 512
#define NBLK 128

typedef unsigned long long u64;

// ---------------- device scratch ----------------
__device__ float g_xpe[(size_t)Tt * Bz * G4];   // [t][b][4H]
__device__ float g_xpd[(size_t)Tt * Bz * G4];
__device__ float g_hse[(size_t)Tt * Hh * Bz];   // [t][h][b]
__device__ float g_hsd[(size_t)Tt * Hh * Bz];
__device__ float g_hA[Hh * Bz];
__device__ float g_hB[Hh * Bz];
__device__ float g_h2A[Hh * Bz];
__device__ float g_h2B[Hh * Bz];
__device__ float g_fcp[(size_t)Tt * Bz * OUTL];
__device__ unsigned g_barCnt[2];

// ---------------- f32x2 helpers ----------------
__device__ __forceinline__ u64 pack2(float lo, float hi) {
    u64 r; asm("mov.b64 %0,{%1,%2};" : "=l"(r) : "f"(lo), "f"(hi)); return r;
}
__device__ __forceinline__ void unpack2(u64 v, float& lo, float& hi) {
    asm("mov.b64 {%0,%1},%2;" : "=f"(lo), "=f"(hi) : "l"(v));
}
__device__ __forceinline__ u64 fma2(u64 a, u64 b, u64 c) {
    u64 d; asm("fma.rn.f32x2 %0,%1,%2,%3;" : "=l"(d) : "l"(a), "l"(b), "l"(c)); return d;
}
__device__ __forceinline__ u64 add2(u64 a, u64 b) {
    u64 d; asm("add.rn.f32x2 %0,%1,%2;" : "=l"(d) : "l"(a), "l"(b)); return d;
}
__device__ __forceinline__ float fsig(float x) { return __fdividef(1.f, 1.f + __expf(-x)); }
__device__ __forceinline__ float ftanh_(float x) { return 2.f * fsig(2.f * x) - 1.f; }
__device__ __forceinline__ unsigned ld_acq(const unsigned* p) {
    unsigned v; asm volatile("ld.acquire.gpu.u32 %0,[%1];" : "=r"(v) : "l"(p) : "memory"); return v;
}
__device__ __forceinline__ void red_rel_add(unsigned* p, unsigned v) {
    asm volatile("red.release.gpu.global.add.u32 [%0],%1;" :: "l"(p), "r"(v) : "memory");
}

// ---------------- init ----------------
__global__ void init_h(const float* __restrict__ h0e, const float* __restrict__ h0d) {
    int i = blockIdx.x * blockDim.x + threadIdx.x;
    if (i < Hh * Bz) {
        int k = i >> 7, b = i & 127;
        g_hA[i]  = h0e[b * Hh + k];
        g_h2A[i] = h0d[b * Hh + k];
    }
}
__global__ void init_bar() {
    if (threadIdx.x < 2) g_barCnt[threadIdx.x] = 0u;
}

// ---------------- input projection GEMM (f32x2) ----------------
template <int MODE>
__global__ void __launch_bounds__(256)
inproj_gemm(const float* __restrict__ A_or_x, const float* __restrict__ W,
            const float* __restrict__ b0v, const float* __restrict__ b1v,
            float* __restrict__ out, int K) {
    __shared__ __align__(16) float As[8][128];
    __shared__ __align__(16) float Bs[8][128];

    const int m0  = blockIdx.y * 128;
    const int n0  = blockIdx.x * 128;
    const int tid = threadIdx.x;
    const int txx = tid & 15;
    const int tyy = tid >> 4;
    const int lrow = tid >> 1;
    const int lkq  = (tid & 1) * 4;
    const int arow = tid >> 5;
    const int acol = (tid & 31) * 4;

    u64 acc[8][4];
#pragma unroll
    for (int i = 0; i < 8; i++)
#pragma unroll
        for (int j = 0; j < 4; j++) acc[i][j] = 0ull;

    float4 aPf, bPf;
    float  aPfS[4];

    if (MODE == 1) {
        aPf = *reinterpret_cast<const float4*>(
            &A_or_x[(size_t)blockIdx.y * Hh * Bz + (size_t)arow * Bz + acol]);
    } else {
        int m = m0 + lrow;
        int tt = m >> 7, b = m & 127;
#pragma unroll
        for (int i = 0; i < 4; i++)
            aPfS[i] = A_or_x[(size_t)b * (INZ * Tt) + (size_t)(lkq + i) * Tt + tt];
    }
    bPf = *reinterpret_cast<const float4*>(&W[(size_t)(n0 + lrow) * K + lkq]);

    for (int k0 = 0; k0 < K; k0 += 8) {
        if (MODE == 1) {
            *reinterpret_cast<float4*>(&As[arow][acol]) = aPf;
        } else {
#pragma unroll
            for (int i = 0; i < 4; i++) As[lkq + i][lrow] = aPfS[i];
        }
        Bs[lkq + 0][lrow] = bPf.x; Bs[lkq + 1][lrow] = bPf.y;
        Bs[lkq + 2][lrow] = bPf.z; Bs[lkq + 3][lrow] = bPf.w;
        __syncthreads();

        int kn = k0 + 8;
        if (kn < K) {
            if (MODE == 1) {
                aPf = *reinterpret_cast<const float4*>(
                    &A_or_x[(size_t)blockIdx.y * Hh * Bz + (size_t)(kn + arow) * Bz + acol]);
            } else {
                int m = m0 + lrow;
                int tt = m >> 7, b = m & 127;
#pragma unroll
                for (int i = 0; i < 4; i++)
                    aPfS[i] = A_or_x[(size_t)b * (INZ * Tt) + (size_t)(kn + lkq + i) * Tt + tt];
            }
            bPf = *reinterpret_cast<const float4*>(&W[(size_t)(n0 + lrow) * K + kn + lkq]);
        }

#pragma unroll
        for (int kk = 0; kk < 8; kk++) {
            float a[8];
            *reinterpret_cast<float4*>(&a[0]) = *reinterpret_cast<const float4*>(&As[kk][tyy * 8]);
            *reinterpret_cast<float4*>(&a[4]) = *reinterpret_cast<const float4*>(&As[kk][tyy * 8 + 4]);
            ulonglong2 bp01 = *reinterpret_cast<const ulonglong2*>(&Bs[kk][txx * 8]);
            ulonglong2 bp23 = *reinterpret_cast<const ulonglong2*>(&Bs[kk][txx * 8 + 4]);
            u64 bp[4] = {bp01.x, bp01.y, bp23.x, bp23.y};
#pragma unroll
            for (int i = 0; i < 8; i++) {
                u64 as = pack2(a[i], a[i]);
#pragma unroll
                for (int j = 0; j < 4; j++)
                    acc[i][j] = fma2(as, bp[j], acc[i][j]);
            }
        }
        __syncthreads();
    }

#pragma unroll
    for (int i = 0; i < 8; i++) {
        int m = m0 + tyy * 8 + i;
#pragma unroll
        for (int j = 0; j < 4; j++) {
            int n = n0 + txx * 8 + 2 * j;
            float lo, hi; unpack2(acc[i][j], lo, hi);
            float2 v = make_float2(lo + b0v[n] + b1v[n], hi + b0v[n + 1] + b1v[n + 1]);
            *reinterpret_cast<float2*>(&out[(size_t)m * G4 + n]) = v;
        }
    }
}

// ---------------- persistent LSTM, crossbar-lean tiling ----------------
// 128 blocks x 256 threads (8 warps). Block owns 4 hidx x 4 gates = 16 weight
// rows, stored UNSPLATTED in smem as ws[k][hh*4+q] (natural (q,q+1) u64 pairs).
// Warp = (gh = warp&1 -> hidx pair, bG = warp>>1 -> 32 b). Lane = (sub = lane>>3
// -> 8 b, s = lane&7 -> k-phase). Lane tile: 8 b x 8 gate-rows, acc = 32 u64.
// Per kk: 2 LDS.128 (h) + 2 LDS.128 (w) feed 32 FFMA2 (2 B/FFMA2 requested).
// k-split reduced via 3x shfl.bfly; epilogue fully parallel (2 h per thread),
// c-state in registers. Grid barrier between steps (R6's).
__global__ void __launch_bounds__(256, 1)
lstm_persistent(const float* __restrict__ xp_all,   // [t][b][2048]
                const float* __restrict__ whh,      // [2048][512]
                const float* __restrict__ c0,       // [b][512]
                float* __restrict__ hbuf0,          // [512][128]
                float* __restrict__ hbuf1,
                float* __restrict__ hs_t,           // [t][512][128]
                int barSel) {
    extern __shared__ char sm_[];
    float* ws = (float*)sm_;                       // [512][16] unsplatted, 32KB
    float* hb = (float*)(sm_ + 32768);             // [2][128][128] 128KB
    float* xs = (float*)(sm_ + 32768 + 131072);    // [128 b][4 q][4 hh] 8KB

    const int tid  = threadIdx.x;
    const int lane = tid & 31;
    const int wrp  = tid >> 5;        // 0..7
    const int s    = lane & 7;        // k-phase
    const int sub  = lane >> 3;       // b-octet within warp
    const int gh   = wrp & 1;         // hidx pair: hh in {2gh, 2gh+1}
    const int bG   = wrp >> 1;        // b-group of 32
    const int hidx0 = blockIdx.x * 4;
    const int b_ep = bG * 32 + lane;  // epilogue b (== bG*32 + sub*8 + s)

    // weights, coalesced over k: ws[k*16 + hh*4 + q]
    for (int r = tid; r < 8192; r += 256) {
        int k = r & 511, idx = r >> 9;
        int hh = idx >> 2, q = idx & 3;
        ws[k * 16 + idx] = whh[(size_t)(q * Hh + hidx0 + hh) * Hh + k];
    }
    // c-state in registers
    float creg[2];
    creg[0] = c0[(size_t)b_ep * Hh + hidx0 + 2 * gh + 0];
    creg[1] = c0[(size_t)b_ep * Hh + hidx0 + 2 * gh + 1];
    __syncthreads();

    unsigned* barCnt = &g_barCnt[barSel];
    const unsigned hb_s = (unsigned)__cvta_generic_to_shared(hb);

    // xp prefetch for t=0: thread stages 2 float4 (fidx = tid*2 + e -> (b,q))
    float4 xr0 = *reinterpret_cast<const float4*>(
        &xp_all[(size_t)(tid * 2 + 0 >> 2) * G4 + ((tid * 2 + 0) & 3) * Hh + hidx0]);
    float4 xr1 = *reinterpret_cast<const float4*>(
        &xp_all[(size_t)(tid * 2 + 1 >> 2) * G4 + ((tid * 2 + 1) & 3) * Hh + hidx0]);

    for (int t = 0; t < Tt; t++) {
        const float* hp = (t & 1) ? hbuf1 : hbuf0;
        float*       hn = (t & 1) ? hbuf0 : hbuf1;

        // issue chunk 0 (64KB; 16 x 16B per thread)
        {
            unsigned sa = hb_s + tid * 16;
            const char* gp = (const char*)hp + tid * 16;
#pragma unroll
            for (int i = 0; i < 16; i++)
                asm volatile("cp.async.cg.shared.global [%0], [%1], 16;"
                             :: "r"(sa + i * 4096), "l"(gp + i * 4096));
            asm volatile("cp.async.commit_group;" ::: "memory");
        }

        u64 acc[8][4];   // [j = b within octet][p = gate-pair]
#pragma unroll
        for (int j = 0; j < 8; j++)
#pragma unroll
            for (int p = 0; p < 4; p++) acc[j][p] = 0ull;

#pragma unroll
        for (int c = 0; c < 4; c++) {
            asm volatile("cp.async.wait_group 0;" ::: "memory");
            __syncthreads();

            if (c < 3) {
                unsigned sa = hb_s + ((c + 1) & 1) * 65536 + tid * 16;
                const char* gp = (const char*)(hp + (c + 1) * 16384) + tid * 16;
#pragma unroll
                for (int i = 0; i < 16; i++)
                    asm volatile("cp.async.cg.shared.global [%0], [%1], 16;"
                                 :: "r"(sa + i * 4096), "l"(gp + i * 4096));
                asm volatile("cp.async.commit_group;" ::: "memory");
            }

            const float* bufc = hb + (c & 1) * 16384 + (size_t)(s * 16) * 128 + bG * 32 + sub * 8;
            const u64*   wrow = (const u64*)(ws + (size_t)(c * 128 + s * 16) * 16 + gh * 8);
#pragma unroll 4
            for (int kk = 0; kk < 16; kk++) {
                const float* hrow = bufc + (size_t)kk * 128;
                float4 h0 = *reinterpret_cast<const float4*>(hrow);
                float4 h1 = *reinterpret_cast<const float4*>(hrow + 4);
                const u64* wr = wrow + (size_t)kk * 8;
                ulonglong2 w01 = *reinterpret_cast<const ulonglong2*>(wr);
                ulonglong2 w23 = *reinterpret_cast<const ulonglong2*>(wr + 2);
                float hv[8] = {h0.x, h0.y, h0.z, h0.w, h1.x, h1.y, h1.z, h1.w};
#pragma unroll
                for (int j = 0; j < 8; j++) {
                    u64 hs = pack2(hv[j], hv[j]);
                    acc[j][0] = fma2(hs, w01.x, acc[j][0]);
                    acc[j][1] = fma2(hs, w01.y, acc[j][1]);
                    acc[j][2] = fma2(hs, w23.x, acc[j][2]);
                    acc[j][3] = fma2(hs, w23.y, acc[j][3]);
                }
            }
        }

        // stage xp tile to smem (read by epilogue)
        *reinterpret_cast<float4*>(&xs[(tid * 2 + 0) * 4]) = xr0;
        *reinterpret_cast<float4*>(&xs[(tid * 2 + 1) * 4]) = xr1;

        // intra-warp k-reduction (xor over s bits); all lanes end with totals
#pragma unroll
        for (int m = 1; m <= 4; m <<= 1)
#pragma unroll
            for (int j = 0; j < 8; j++)
#pragma unroll
                for (int p = 0; p < 4; p++)
                    acc[j][p] = add2(acc[j][p],
                                     __shfl_xor_sync(0xffffffffu, acc[j][p], m));

        __syncthreads();   // xs visible

        // select j == s (predicated, no dynamic indexing)
        u64 a0 = 0, a1 = 0, a2 = 0, a3 = 0;
#pragma unroll
        for (int j = 0; j < 8; j++)
            if (j == s) { a0 = acc[j][0]; a1 = acc[j][1]; a2 = acc[j][2]; a3 = acc[j][3]; }

        // epilogue: 2 h values per thread, c in registers
#pragma unroll
        for (int hl = 0; hl < 2; hl++) {
            float gi_, gf_, gg_, go_;
            unpack2(hl ? a2 : a0, gi_, gf_);
            unpack2(hl ? a3 : a1, gg_, go_);
            int hx = 2 * gh + hl;
            const float* xb = xs + b_ep * 16 + hx;
            float gi = gi_ + xb[0];
            float gf = gf_ + xb[4];
            float gg = gg_ + xb[8];
            float go = go_ + xb[12];
            float cc = fsig(gf) * creg[hl] + fsig(gi) * ftanh_(gg);
            creg[hl] = cc;
            float h = fsig(go) * ftanh_(cc);
            hn[(hidx0 + hx) * Bz + b_ep] = h;
            hs_t[(size_t)t * Hh * Bz + (hidx0 + hx) * Bz + b_ep] = h;
        }

        // prefetch next step's xp before the barrier
        if (t + 1 < Tt) {
            const float* xpn = xp_all + (size_t)(t + 1) * Bz * G4;
            xr0 = *reinterpret_cast<const float4*>(
                &xpn[(size_t)(tid * 2 + 0 >> 2) * G4 + ((tid * 2 + 0) & 3) * Hh + hidx0]);
            xr1 = *reinterpret_cast<const float4*>(
                &xpn[(size_t)(tid * 2 + 1 >> 2) * G4 + ((tid * 2 + 1) & 3) * Hh + hidx0]);

            __syncthreads();
            if (tid == 0) {
                red_rel_add(barCnt, 1u);
                unsigned target = (unsigned)(NBLK * (t + 1));
                while (ld_acq(barCnt) < target) {}
            }
            __syncthreads();
        }
    }
}

// ---------------- encoder output transpose: out[b][h][t] = hse_t[t][h][b] ----------------
__global__ void __launch_bounds__(256)
enc_transpose(const float* __restrict__ hs_t, float* __restrict__ out) {
    __shared__ float tile[32][33];
    int t0 = blockIdx.x * 32, b0 = blockIdx.y * 32, h = blockIdx.z;
    int tx = threadIdx.x & 31, ty = threadIdx.x >> 5;
#pragma unroll
    for (int i = ty; i < 32; i += 8)
        tile[i][tx] = hs_t[(size_t)(t0 + i) * (Hh * Bz) + (size_t)h * Bz + b0 + tx];
    __syncthreads();
#pragma unroll
    for (int i = ty; i < 32; i += 8)
        out[(size_t)(b0 + i) * (Hh * Tt) + (size_t)h * Tt + t0 + tx] = tile[tx][i];
}

// ---------------- FC partial GEMM (f32x2, k-split over t) ----------------
__global__ void __launch_bounds__(256)
fc_partial(const float* __restrict__ hsd_t, const float* __restrict__ Wfc) {
    const int t  = blockIdx.y;
    const int o0 = blockIdx.x * 128;
    const int tid = threadIdx.x;
    const int txx = tid & 15;
    const int tyy = tid >> 4;
    const int lrow = tid >> 1;
    const int lkq  = (tid & 1) * 4;
    const int arow = tid >> 5;
    const int acol = (tid & 31) * 4;

    __shared__ __align__(16) float As[8][128];
    __shared__ __align__(16) float Bs[8][128];

    u64 acc[8][4];
#pragma unroll
    for (int i = 0; i < 8; i++)
#pragma unroll
        for (int j = 0; j < 4; j++) acc[i][j] = 0ull;

    const float* Abase = hsd_t + (size_t)t * (Hh * Bz);

    for (int h0 = 0; h0 < Hh; h0 += 8) {
        *reinterpret_cast<float4*>(&As[arow][acol]) =
            *reinterpret_cast<const float4*>(&Abase[(size_t)(h0 + arow) * Bz + acol]);
#pragma unroll
        for (int i = 0; i < 4; i++)
            Bs[lkq + i][lrow] = Wfc[(size_t)(o0 + lrow) * (Hh * Tt) + (size_t)(h0 + lkq + i) * Tt + t];
        __syncthreads();
#pragma unroll
        for (int kk = 0; kk < 8; kk++) {
            float a[8];
            *reinterpret_cast<float4*>(&a[0]) = *reinterpret_cast<const float4*>(&As[kk][tyy * 8]);
            *reinterpret_cast<float4*>(&a[4]) = *reinterpret_cast<const float4*>(&As[kk][tyy * 8 + 4]);
            ulonglong2 bp01 = *reinterpret_cast<const ulonglong2*>(&Bs[kk][txx * 8]);
            ulonglong2 bp23 = *reinterpret_cast<const ulonglong2*>(&Bs[kk][txx * 8 + 4]);
            u64 bp[4] = {bp01.x, bp01.y, bp23.x, bp23.y};
#pragma unroll
            for (int i = 0; i < 8; i++) {
                u64 as = pack2(a[i], a[i]);
#pragma unroll
                for (int j = 0; j < 4; j++)
                    acc[i][j] = fma2(as, bp[j], acc[i][j]);
            }
        }
        __syncthreads();
    }

    float* part = g_fcp + (size_t)t * (Bz * OUTL);
#pragma unroll
    for (int i = 0; i < 8; i++) {
        int b = tyy * 8 + i;
#pragma unroll
        for (int j = 0; j < 4; j++) {
            float lo, hi; unpack2(acc[i][j], lo, hi);
            *reinterpret_cast<float2*>(&part[(size_t)b * OUTL + o0 + txx * 8 + 2 * j]) =
                make_float2(lo, hi);
        }
    }
}

__global__ void fc_reduce(const float* __restrict__ bfc, float* __restrict__ decoded) {
    int i = blockIdx.x * blockDim.x + threadIdx.x;
    if (i >= Bz * OUTL) return;
    float s = bfc[i & (OUTL - 1)];
    for (int t = 0; t < Tt; t++) s += g_fcp[(size_t)t * (Bz * OUTL) + i];
    decoded[i] = s;
}

// ---------------- launch ----------------
extern "C" void kernel_launch(void* const* d_in, const int* in_sizes, int n_in,
                              void* d_out, int out_size) {
    const float* x     = (const float*)d_in[0];
    const float* h0e   = (const float*)d_in[1];
    const float* c0e   = (const float*)d_in[2];
    const float* Wih_e = (const float*)d_in[3];
    const float* Whh_e = (const float*)d_in[4];
    const float* bih_e = (const float*)d_in[5];
    const float* bhh_e = (const float*)d_in[6];
    const float* h0d   = (const float*)d_in[7];
    const float* c0d   = (const float*)d_in[8];
    const float* Wih_d = (const float*)d_in[9];
    const float* Whh_d = (const float*)d_in[10];
    const float* bih_d = (const float*)d_in[11];
    const float* bhh_d = (const float*)d_in[12];
    const float* Wfc   = (const float*)d_in[13];
    const float* bfc   = (const float*)d_in[14];

    float* out = (float*)d_out;
    float* enc_out = out;
    float* decoded = out + (size_t)Bz * Hh * Tt;

    float *xpe, *xpd, *hse, *hsd, *hA, *hB, *h2A, *h2B;
    cudaGetSymbolAddress((void**)&xpe, g_xpe);
    cudaGetSymbolAddress((void**)&xpd, g_xpd);
    cudaGetSymbolAddress((void**)&hse, g_hse);
    cudaGetSymbolAddress((void**)&hsd, g_hsd);
    cudaGetSymbolAddress((void**)&hA,  g_hA);
    cudaGetSymbolAddress((void**)&hB,  g_hB);
    cudaGetSymbolAddress((void**)&h2A, g_h2A);
    cudaGetSymbolAddress((void**)&h2B, g_h2B);

    const int SMEM = 32768 + 131072 + 8192;   // 172032
    cudaFuncSetAttribute(lstm_persistent, cudaFuncAttributeMaxDynamicSharedMemorySize, SMEM);

    init_h<<<(Hh * Bz + 255) / 256, 256>>>(h0e, h0d);
    init_bar<<<1, 32>>>();

    inproj_gemm<0><<<dim3(16, 256), 256>>>(x, Wih_e, bih_e, bhh_e, xpe, INZ);

    lstm_persistent<<<NBLK, 256, SMEM>>>(xpe, Whh_e, c0e, hA, hB, hse, 0);

    inproj_gemm<1><<<dim3(16, 256), 256>>>(hse, Wih_d, bih_d, bhh_d, xpd, Hh);

    lstm_persistent<<<NBLK, 256, SMEM>>>(xpd, Whh_d, c0d, h2A, h2B, hsd, 1);

    enc_transpose<<<dim3(Tt / 32, Bz / 32, Hh), 256>>>(hse, enc_out);

    fc_partial<<<dim3(4, Tt), 256>>>(hsd, Wfc);
    fc_reduce<<<(Bz * OUTL + 255) / 256, 256>>>(bfc, decoded);
}

// round 8
// speedup vs baseline: 2.7443x; 2.7443x over previous
#include <cuda_runtime.h>
#include <math.h>

#define Bz   128
#define Hh   512
#define G4   2048
#define Tt   256
#define INZ  64
#define OUTL 512
#define NBLK 128

typedef unsigned long long u64;

// ---------------- device scratch ----------------
__device__ float g_xpe[(size_t)Tt * Bz * G4];   // [t][b][4H]
__device__ float g_xpd[(size_t)Tt * Bz * G4];
__device__ float g_hse[(size_t)Tt * Hh * Bz];   // [t][h][b]
__device__ float g_hsd[(size_t)Tt * Hh * Bz];
__device__ float g_hA[Hh * Bz];
__device__ float g_hB[Hh * Bz];
__device__ float g_h2A[Hh * Bz];
__device__ float g_h2B[Hh * Bz];
__device__ float g_fcp[(size_t)Tt * Bz * OUTL];
__device__ unsigned g_barCnt[2];

// ---------------- f32x2 helpers ----------------
__device__ __forceinline__ u64 pack2(float lo, float hi) {
    u64 r; asm("mov.b64 %0,{%1,%2};" : "=l"(r) : "f"(lo), "f"(hi)); return r;
}
__device__ __forceinline__ void unpack2(u64 v, float& lo, float& hi) {
    asm("mov.b64 {%0,%1},%2;" : "=f"(lo), "=f"(hi) : "l"(v));
}
__device__ __forceinline__ u64 fma2(u64 a, u64 b, u64 c) {
    u64 d; asm("fma.rn.f32x2 %0,%1,%2,%3;" : "=l"(d) : "l"(a), "l"(b), "l"(c)); return d;
}
__device__ __forceinline__ u64 add2(u64 a, u64 b) {
    u64 d; asm("add.rn.f32x2 %0,%1,%2;" : "=l"(d) : "l"(a), "l"(b)); return d;
}
__device__ __forceinline__ float fsig(float x) { return __fdividef(1.f, 1.f + __expf(-x)); }
__device__ __forceinline__ float ftanh_(float x) { return 2.f * fsig(2.f * x) - 1.f; }
__device__ __forceinline__ unsigned ld_acq(const unsigned* p) {
    unsigned v; asm volatile("ld.acquire.gpu.u32 %0,[%1];" : "=r"(v) : "l"(p) : "memory"); return v;
}
__device__ __forceinline__ void red_rel_add(unsigned* p, unsigned v) {
    asm volatile("red.release.gpu.global.add.u32 [%0],%1;" :: "l"(p), "r"(v) : "memory");
}

// ---------------- init ----------------
__global__ void init_h(const float* __restrict__ h0e, const float* __restrict__ h0d) {
    int i = blockIdx.x * blockDim.x + threadIdx.x;
    if (i < Hh * Bz) {
        int k = i >> 7, b = i & 127;
        g_hA[i]  = h0e[b * Hh + k];
        g_h2A[i] = h0d[b * Hh + k];
    }
}
__global__ void init_bar() {
    if (threadIdx.x < 2) g_barCnt[threadIdx.x] = 0u;
}

// ---------------- input projection GEMM (f32x2) ----------------
template <int MODE>
__global__ void __launch_bounds__(256)
inproj_gemm(const float* __restrict__ A_or_x, const float* __restrict__ W,
            const float* __restrict__ b0v, const float* __restrict__ b1v,
            float* __restrict__ out, int K) {
    __shared__ __align__(16) float As[8][128];
    __shared__ __align__(16) float Bs[8][128];

    const int m0  = blockIdx.y * 128;
    const int n0  = blockIdx.x * 128;
    const int tid = threadIdx.x;
    const int txx = tid & 15;
    const int tyy = tid >> 4;
    const int lrow = tid >> 1;
    const int lkq  = (tid & 1) * 4;
    const int arow = tid >> 5;
    const int acol = (tid & 31) * 4;

    u64 acc[8][4];
#pragma unroll
    for (int i = 0; i < 8; i++)
#pragma unroll
        for (int j = 0; j < 4; j++) acc[i][j] = 0ull;

    float4 aPf, bPf;
    float  aPfS[4];

    if (MODE == 1) {
        aPf = *reinterpret_cast<const float4*>(
            &A_or_x[(size_t)blockIdx.y * Hh * Bz + (size_t)arow * Bz + acol]);
    } else {
        int m = m0 + lrow;
        int tt = m >> 7, b = m & 127;
#pragma unroll
        for (int i = 0; i < 4; i++)
            aPfS[i] = A_or_x[(size_t)b * (INZ * Tt) + (size_t)(lkq + i) * Tt + tt];
    }
    bPf = *reinterpret_cast<const float4*>(&W[(size_t)(n0 + lrow) * K + lkq]);

    for (int k0 = 0; k0 < K; k0 += 8) {
        if (MODE == 1) {
            *reinterpret_cast<float4*>(&As[arow][acol]) = aPf;
        } else {
#pragma unroll
            for (int i = 0; i < 4; i++) As[lkq + i][lrow] = aPfS[i];
        }
        Bs[lkq + 0][lrow] = bPf.x; Bs[lkq + 1][lrow] = bPf.y;
        Bs[lkq + 2][lrow] = bPf.z; Bs[lkq + 3][lrow] = bPf.w;
        __syncthreads();

        int kn = k0 + 8;
        if (kn < K) {
            if (MODE == 1) {
                aPf = *reinterpret_cast<const float4*>(
                    &A_or_x[(size_t)blockIdx.y * Hh * Bz + (size_t)(kn + arow) * Bz + acol]);
            } else {
                int m = m0 + lrow;
                int tt = m >> 7, b = m & 127;
#pragma unroll
                for (int i = 0; i < 4; i++)
                    aPfS[i] = A_or_x[(size_t)b * (INZ * Tt) + (size_t)(kn + lkq + i) * Tt + tt];
            }
            bPf = *reinterpret_cast<const float4*>(&W[(size_t)(n0 + lrow) * K + kn + lkq]);
        }

#pragma unroll
        for (int kk = 0; kk < 8; kk++) {
            float a[8];
            *reinterpret_cast<float4*>(&a[0]) = *reinterpret_cast<const float4*>(&As[kk][tyy * 8]);
            *reinterpret_cast<float4*>(&a[4]) = *reinterpret_cast<const float4*>(&As[kk][tyy * 8 + 4]);
            ulonglong2 bp01 = *reinterpret_cast<const ulonglong2*>(&Bs[kk][txx * 8]);
            ulonglong2 bp23 = *reinterpret_cast<const ulonglong2*>(&Bs[kk][txx * 8 + 4]);
            u64 bp[4] = {bp01.x, bp01.y, bp23.x, bp23.y};
#pragma unroll
            for (int i = 0; i < 8; i++) {
                u64 as = pack2(a[i], a[i]);
#pragma unroll
                for (int j = 0; j < 4; j++)
                    acc[i][j] = fma2(as, bp[j], acc[i][j]);
            }
        }
        __syncthreads();
    }

#pragma unroll
    for (int i = 0; i < 8; i++) {
        int m = m0 + tyy * 8 + i;
#pragma unroll
        for (int j = 0; j < 4; j++) {
            int n = n0 + txx * 8 + 2 * j;
            float lo, hi; unpack2(acc[i][j], lo, hi);
            float2 v = make_float2(lo + b0v[n] + b1v[n], hi + b0v[n + 1] + b1v[n + 1]);
            *reinterpret_cast<float2*>(&out[(size_t)m * G4 + n]) = v;
        }
    }
}

// ---------------- persistent LSTM, 1 B/FMA inner loop ----------------
// 128 blocks x 512 threads (16 warps). Block owns 4 hidx x 4 gates = 16 weight
// rows, smem ws[k][hh*4+q] fp32 (natural (q,q+1) u64 pairs, 32KB). Warp w owns
// k-rows w*8..w*8+8 of each 128-row chunk (16-way k-split). Lane (rh=lane>>4,
// bo=lane&15): tile = 8 b (bo*8..) x 8 gate-rows (hh=2rh,2rh+1 x 4q). Per kk:
// 4 LDS.128 + 8 pack2 + 32 FFMA2 = 64B per 64 lane-FMA (1 B/FMA on the smem
// crossbar = the FFMA2 floor). Reduction: all warps dump accs into the freed
// h-chunk buffer (stride-33 u64), then 512 threads each sum 16 partials for
// one (b,hh) cell; fully parallel epilogue, c-state per-thread in registers.
__global__ void __launch_bounds__(512, 1)
lstm_persistent(const float* __restrict__ xp_all,   // [t][b][2048]
                const float* __restrict__ whh,      // [2048][512]
                const float* __restrict__ c0,       // [b][512]
                float* __restrict__ hbuf0,          // [512][128]
                float* __restrict__ hbuf1,
                float* __restrict__ hs_t,           // [t][512][128]
                int barSel) {
    extern __shared__ char sm_[];
    float* ws    = (float*)sm_;                    // [512][16]  32KB
    float* hb    = (float*)(sm_ + 32768);          // [2][128][128] 128KB (reused as red)
    u64*   red64 = (u64*)(sm_ + 32768);            // [16][1056] u64 = 132KB
    float* xs    = (float*)(sm_ + 32768 + 135168); // [128][20] 10KB

    const int tid  = threadIdx.x;
    const int lane = tid & 31;
    const int wrp  = tid >> 5;        // 0..15 : k-slice
    const int rh   = lane >> 4;       // 0/1 : hh half
    const int bo   = lane & 15;       // b-octet
    const int hidx0 = blockIdx.x * 4;

    // epilogue identity: thread t <-> (b = t&127, hh = t>>7)
    const int eb  = tid & 127;
    const int ehh = tid >> 7;
    const int erh = ehh >> 1, ehp = ehh & 1;
    const int ebo = eb >> 3,  ej  = eb & 7;
    const int lane_src = erh * 16 + ebo;
    const int idx0 = ej * 4 + ehp * 2;

    // weights: ws[k*16 + hh*4 + q], coalesced over k
    for (int r = tid; r < 8192; r += 512) {
        int k = r & 511, idx = r >> 9;
        int hh = idx >> 2, q = idx & 3;
        ws[k * 16 + idx] = whh[(size_t)(q * Hh + hidx0 + hh) * Hh + k];
    }
    // c-state: 1 per thread
    float creg = c0[(size_t)eb * Hh + hidx0 + ehh];
    __syncthreads();

    unsigned* barCnt = &g_barCnt[barSel];
    const unsigned hb_s = (unsigned)__cvta_generic_to_shared(hb);

    // xp prefetch for t=0: thread stages float4 for (b = tid>>2, q = tid&3)
    float4 xr = *reinterpret_cast<const float4*>(
        &xp_all[(size_t)(tid >> 2) * G4 + (tid & 3) * Hh + hidx0]);

    for (int t = 0; t < Tt; t++) {
        const float* hp = (t & 1) ? hbuf1 : hbuf0;
        float*       hn = (t & 1) ? hbuf0 : hbuf1;

        // issue chunk 0 (64KB; 8 x 16B per thread)
        {
            unsigned sa = hb_s + tid * 16;
            const char* gp = (const char*)hp + tid * 16;
#pragma unroll
            for (int i = 0; i < 8; i++)
                asm volatile("cp.async.cg.shared.global [%0], [%1], 16;"
                             :: "r"(sa + i * 8192), "l"(gp + i * 8192));
            asm volatile("cp.async.commit_group;" ::: "memory");
        }

        u64 acc[8][4];   // [j = b in octet][p: (hh = 2rh + (p>>1), qpair = p&1)]
#pragma unroll
        for (int j = 0; j < 8; j++)
#pragma unroll
            for (int p = 0; p < 4; p++) acc[j][p] = 0ull;

#pragma unroll
        for (int c = 0; c < 4; c++) {
            asm volatile("cp.async.wait_group 0;" ::: "memory");
            __syncthreads();

            if (c < 3) {
                unsigned sa = hb_s + ((c + 1) & 1) * 65536 + tid * 16;
                const char* gp = (const char*)(hp + (c + 1) * 16384) + tid * 16;
#pragma unroll
                for (int i = 0; i < 8; i++)
                    asm volatile("cp.async.cg.shared.global [%0], [%1], 16;"
                                 :: "r"(sa + i * 8192), "l"(gp + i * 8192));
                asm volatile("cp.async.commit_group;" ::: "memory");
            }

            const float* bufk = hb + (c & 1) * 16384 + (size_t)(wrp * 8) * 128 + bo * 8;
            const float* wsk  = ws + (size_t)(c * 128 + wrp * 8) * 16 + rh * 8;
#pragma unroll
            for (int kk = 0; kk < 8; kk++) {
                float4 h0 = *reinterpret_cast<const float4*>(bufk + (size_t)kk * 128);
                float4 h1 = *reinterpret_cast<const float4*>(bufk + (size_t)kk * 128 + 4);
                ulonglong2 wa = *reinterpret_cast<const ulonglong2*>(wsk + (size_t)kk * 16);
                ulonglong2 wb = *reinterpret_cast<const ulonglong2*>(wsk + (size_t)kk * 16 + 4);
                float hv[8] = {h0.x, h0.y, h0.z, h0.w, h1.x, h1.y, h1.z, h1.w};
#pragma unroll
                for (int j = 0; j < 8; j++) {
                    u64 hs = pack2(hv[j], hv[j]);
                    acc[j][0] = fma2(hs, wa.x, acc[j][0]);
                    acc[j][1] = fma2(hs, wa.y, acc[j][1]);
                    acc[j][2] = fma2(hs, wb.x, acc[j][2]);
                    acc[j][3] = fma2(hs, wb.y, acc[j][3]);
                }
            }
        }

        __syncthreads();   // all chunks consumed; hb free for reduction

        // stage xp tile (padded stride 20 floats per b)
        *reinterpret_cast<float4*>(&xs[(tid >> 2) * 20 + (tid & 3) * 4]) = xr;

        // dump partials: warp wrp, lane -> red64[wrp*1056 + lane*33 + j*4 + p]
        {
            u64* rp = red64 + (size_t)wrp * 1056 + (size_t)lane * 33;
#pragma unroll
            for (int j = 0; j < 8; j++)
#pragma unroll
                for (int p = 0; p < 4; p++) rp[j * 4 + p] = acc[j][p];
        }
        __syncthreads();

        // per-thread: sum 16 k-slice partials for cell (eb, ehh)
        u64 s0 = 0ull, s1 = 0ull;
        {
            const u64* rp = red64 + (size_t)lane_src * 33 + idx0;
#pragma unroll
            for (int g = 0; g < 16; g++) {
                s0 = add2(s0, rp[(size_t)g * 1056]);
                s1 = add2(s1, rp[(size_t)g * 1056 + 1]);
            }
        }

        // epilogue (gate order i,f,g,o)
        {
            float gi_, gf_, gg_, go_;
            unpack2(s0, gi_, gf_);
            unpack2(s1, gg_, go_);
            const float* xb = xs + eb * 20 + ehh;
            float gi = gi_ + xb[0];
            float gf = gf_ + xb[4];
            float gg = gg_ + xb[8];
            float go = go_ + xb[12];
            float cc = fsig(gf) * creg + fsig(gi) * ftanh_(gg);
            creg = cc;
            float h = fsig(go) * ftanh_(cc);
            int off = (hidx0 + ehh) * Bz + eb;
            hn[off] = h;
            hs_t[(size_t)t * Hh * Bz + off] = h;
        }

        // prefetch next step's xp (independent of h)
        if (t + 1 < Tt) {
            xr = *reinterpret_cast<const float4*>(
                &xp_all[(size_t)(t + 1) * Bz * G4 +
                        (size_t)(tid >> 2) * G4 + (tid & 3) * Hh + hidx0]);

            __threadfence();
            __syncthreads();
            if (tid == 0) {
                red_rel_add(barCnt, 1u);
                unsigned target = (unsigned)(NBLK * (t + 1));
                while (ld_acq(barCnt) < target) {}
            }
            __syncthreads();
        }
    }
}

// ---------------- encoder output transpose: out[b][h][t] = hse_t[t][h][b] ----------------
__global__ void __launch_bounds__(256)
enc_transpose(const float* __restrict__ hs_t, float* __restrict__ out) {
    __shared__ float tile[32][33];
    int t0 = blockIdx.x * 32, b0 = blockIdx.y * 32, h = blockIdx.z;
    int tx = threadIdx.x & 31, ty = threadIdx.x >> 5;
#pragma unroll
    for (int i = ty; i < 32; i += 8)
        tile[i][tx] = hs_t[(size_t)(t0 + i) * (Hh * Bz) + (size_t)h * Bz + b0 + tx];
    __syncthreads();
#pragma unroll
    for (int i = ty; i < 32; i += 8)
        out[(size_t)(b0 + i) * (Hh * Tt) + (size_t)h * Tt + t0 + tx] = tile[tx][i];
}

// ---------------- FC partial GEMM (f32x2, k-split over t) ----------------
__global__ void __launch_bounds__(256)
fc_partial(const float* __restrict__ hsd_t, const float* __restrict__ Wfc) {
    const int t  = blockIdx.y;
    const int o0 = blockIdx.x * 128;
    const int tid = threadIdx.x;
    const int txx = tid & 15;
    const int tyy = tid >> 4;
    const int lrow = tid >> 1;
    const int lkq  = (tid & 1) * 4;
    const int arow = tid >> 5;
    const int acol = (tid & 31) * 4;

    __shared__ __align__(16) float As[8][128];
    __shared__ __align__(16) float Bs[8][128];

    u64 acc[8][4];
#pragma unroll
    for (int i = 0; i < 8; i++)
#pragma unroll
        for (int j = 0; j < 4; j++) acc[i][j] = 0ull;

    const float* Abase = hsd_t + (size_t)t * (Hh * Bz);

    for (int h0 = 0; h0 < Hh; h0 += 8) {
        *reinterpret_cast<float4*>(&As[arow][acol]) =
            *reinterpret_cast<const float4*>(&Abase[(size_t)(h0 + arow) * Bz + acol]);
#pragma unroll
        for (int i = 0; i < 4; i++)
            Bs[lkq + i][lrow] = Wfc[(size_t)(o0 + lrow) * (Hh * Tt) + (size_t)(h0 + lkq + i) * Tt + t];
        __syncthreads();
#pragma unroll
        for (int kk = 0; kk < 8; kk++) {
            float a[8];
            *reinterpret_cast<float4*>(&a[0]) = *reinterpret_cast<const float4*>(&As[kk][tyy * 8]);
            *reinterpret_cast<float4*>(&a[4]) = *reinterpret_cast<const float4*>(&As[kk][tyy * 8 + 4]);
            ulonglong2 bp01 = *reinterpret_cast<const ulonglong2*>(&Bs[kk][txx * 8]);
            ulonglong2 bp23 = *reinterpret_cast<const ulonglong2*>(&Bs[kk][txx * 8 + 4]);
            u64 bp[4] = {bp01.x, bp01.y, bp23.x, bp23.y};
#pragma unroll
            for (int i = 0; i < 8; i++) {
                u64 as = pack2(a[i], a[i]);
#pragma unroll
                for (int j = 0; j < 4; j++)
                    acc[i][j] = fma2(as, bp[j], acc[i][j]);
            }
        }
        __syncthreads();
    }

    float* part = g_fcp + (size_t)t * (Bz * OUTL);
#pragma unroll
    for (int i = 0; i < 8; i++) {
        int b = tyy * 8 + i;
#pragma unroll
        for (int j = 0; j < 4; j++) {
            float lo, hi; unpack2(acc[i][j], lo, hi);
            *reinterpret_cast<float2*>(&part[(size_t)b * OUTL + o0 + txx * 8 + 2 * j]) =
                make_float2(lo, hi);
        }
    }
}

__global__ void fc_reduce(const float* __restrict__ bfc, float* __restrict__ decoded) {
    int i = blockIdx.x * blockDim.x + threadIdx.x;
    if (i >= Bz * OUTL) return;
    float s = bfc[i & (OUTL - 1)];
    for (int t = 0; t < Tt; t++) s += g_fcp[(size_t)t * (Bz * OUTL) + i];
    decoded[i] = s;
}

// ---------------- launch ----------------
extern "C" void kernel_launch(void* const* d_in, const int* in_sizes, int n_in,
                              void* d_out, int out_size) {
    const float* x     = (const float*)d_in[0];
    const float* h0e   = (const float*)d_in[1];
    const float* c0e   = (const float*)d_in[2];
    const float* Wih_e = (const float*)d_in[3];
    const float* Whh_e = (const float*)d_in[4];
    const float* bih_e = (const float*)d_in[5];
    const float* bhh_e = (const float*)d_in[6];
    const float* h0d   = (const float*)d_in[7];
    const float* c0d   = (const float*)d_in[8];
    const float* Wih_d = (const float*)d_in[9];
    const float* Whh_d = (const float*)d_in[10];
    const float* bih_d = (const float*)d_in[11];
    const float* bhh_d = (const float*)d_in[12];
    const float* Wfc   = (const float*)d_in[13];
    const float* bfc   = (const float*)d_in[14];

    float* out = (float*)d_out;
    float* enc_out = out;
    float* decoded = out + (size_t)Bz * Hh * Tt;

    float *xpe, *xpd, *hse, *hsd, *hA, *hB, *h2A, *h2B;
    cudaGetSymbolAddress((void**)&xpe, g_xpe);
    cudaGetSymbolAddress((void**)&xpd, g_xpd);
    cudaGetSymbolAddress((void**)&hse, g_hse);
    cudaGetSymbolAddress((void**)&hsd, g_hsd);
    cudaGetSymbolAddress((void**)&hA,  g_hA);
    cudaGetSymbolAddress((void**)&hB,  g_hB);
    cudaGetSymbolAddress((void**)&h2A, g_h2A);
    cudaGetSymbolAddress((void**)&h2B, g_h2B);

    const int SMEM = 32768 + 135168 + 10240;   // 178176
    cudaFuncSetAttribute(lstm_persistent, cudaFuncAttributeMaxDynamicSharedMemorySize, SMEM);

    init_h<<<(Hh * Bz + 255) / 256, 256>>>(h0e, h0d);
    init_bar<<<1, 32>>>();

    inproj_gemm<0><<<dim3(16, 256), 256>>>(x, Wih_e, bih_e, bhh_e, xpe, INZ);

    lstm_persistent<<<NBLK, 512, SMEM>>>(xpe, Whh_e, c0e, hA, hB, hse, 0);

    inproj_gemm<1><<<dim3(16, 256), 256>>>(hse, Wih_d, bih_d, bhh_d, xpd, Hh);

    lstm_persistent<<<NBLK, 512, SMEM>>>(xpd, Whh_d, c0d, h2A, h2B, hsd, 1);

    enc_transpose<<<dim3(Tt / 32, Bz / 32, Hh), 256>>>(hse, enc_out);

    fc_partial<<<dim3(4, Tt), 256>>>(hsd, Wfc);
    fc_reduce<<<(Bz * OUTL + 255) / 256, 256>>>(bfc, decoded);
}

// round 9
// speedup vs baseline: 2.7561x; 1.0043x over previous
#include <cuda_runtime.h>
#include <math.h>

#define Bz   128
#define Hh   512
#define G4   2048
#define Tt   256
#define INZ  64
#define OUTL 512
#define NBLK 128

typedef unsigned long long u64;

// ---------------- device scratch ----------------
__device__ float g_xpe[(size_t)Tt * Bz * G4];   // [t][b][4H]
__device__ float g_xpd[(size_t)Tt * Bz * G4];
__device__ float g_hse[(size_t)Tt * Hh * Bz];   // [t][h][b] (also h ring buffer)
__device__ float g_hsd[(size_t)Tt * Hh * Bz];
__device__ float g_hA[Hh * Bz];                 // initial h (encoder)
__device__ float g_h2A[Hh * Bz];                // initial h (decoder)
__device__ float g_fcp[(size_t)Tt * Bz * OUTL];
__device__ unsigned g_ck[8];                    // [layer][chunk] producer counters

// ---------------- f32x2 helpers ----------------
__device__ __forceinline__ u64 pack2(float lo, float hi) {
    u64 r; asm("mov.b64 %0,{%1,%2};" : "=l"(r) : "f"(lo), "f"(hi)); return r;
}
__device__ __forceinline__ void unpack2(u64 v, float& lo, float& hi) {
    asm("mov.b64 {%0,%1},%2;" : "=f"(lo), "=f"(hi) : "l"(v));
}
__device__ __forceinline__ u64 fma2(u64 a, u64 b, u64 c) {
    u64 d; asm("fma.rn.f32x2 %0,%1,%2,%3;" : "=l"(d) : "l"(a), "l"(b), "l"(c)); return d;
}
__device__ __forceinline__ u64 add2(u64 a, u64 b) {
    u64 d; asm("add.rn.f32x2 %0,%1,%2;" : "=l"(d) : "l"(a), "l"(b)); return d;
}
__device__ __forceinline__ float fsig(float x) { return __fdividef(1.f, 1.f + __expf(-x)); }
__device__ __forceinline__ float ftanh_(float x) { return 2.f * fsig(2.f * x) - 1.f; }
__device__ __forceinline__ unsigned ld_acq(const unsigned* p) {
    unsigned v; asm volatile("ld.acquire.gpu.u32 %0,[%1];" : "=r"(v) : "l"(p) : "memory"); return v;
}
__device__ __forceinline__ void red_rel_add(unsigned* p, unsigned v) {
    asm volatile("red.release.gpu.global.add.u32 [%0],%1;" :: "l"(p), "r"(v) : "memory");
}

// ---------------- init ----------------
__global__ void init_h(const float* __restrict__ h0e, const float* __restrict__ h0d) {
    int i = blockIdx.x * blockDim.x + threadIdx.x;
    if (i < Hh * Bz) {
        int k = i >> 7, b = i & 127;
        g_hA[i]  = h0e[b * Hh + k];
        g_h2A[i] = h0d[b * Hh + k];
    }
}
__global__ void init_bar() {
    if (threadIdx.x < 8) g_ck[threadIdx.x] = 0u;
}

// ---------------- input projection GEMM (f32x2) ----------------
template <int MODE>
__global__ void __launch_bounds__(256)
inproj_gemm(const float* __restrict__ A_or_x, const float* __restrict__ W,
            const float* __restrict__ b0v, const float* __restrict__ b1v,
            float* __restrict__ out, int K) {
    __shared__ __align__(16) float As[8][128];
    __shared__ __align__(16) float Bs[8][128];

    const int m0  = blockIdx.y * 128;
    const int n0  = blockIdx.x * 128;
    const int tid = threadIdx.x;
    const int txx = tid & 15;
    const int tyy = tid >> 4;
    const int lrow = tid >> 1;
    const int lkq  = (tid & 1) * 4;
    const int arow = tid >> 5;
    const int acol = (tid & 31) * 4;

    u64 acc[8][4];
#pragma unroll
    for (int i = 0; i < 8; i++)
#pragma unroll
        for (int j = 0; j < 4; j++) acc[i][j] = 0ull;

    float4 aPf, bPf;
    float  aPfS[4];

    if (MODE == 1) {
        aPf = *reinterpret_cast<const float4*>(
            &A_or_x[(size_t)blockIdx.y * Hh * Bz + (size_t)arow * Bz + acol]);
    } else {
        int m = m0 + lrow;
        int tt = m >> 7, b = m & 127;
#pragma unroll
        for (int i = 0; i < 4; i++)
            aPfS[i] = A_or_x[(size_t)b * (INZ * Tt) + (size_t)(lkq + i) * Tt + tt];
    }
    bPf = *reinterpret_cast<const float4*>(&W[(size_t)(n0 + lrow) * K + lkq]);

    for (int k0 = 0; k0 < K; k0 += 8) {
        if (MODE == 1) {
            *reinterpret_cast<float4*>(&As[arow][acol]) = aPf;
        } else {
#pragma unroll
            for (int i = 0; i < 4; i++) As[lkq + i][lrow] = aPfS[i];
        }
        Bs[lkq + 0][lrow] = bPf.x; Bs[lkq + 1][lrow] = bPf.y;
        Bs[lkq + 2][lrow] = bPf.z; Bs[lkq + 3][lrow] = bPf.w;
        __syncthreads();

        int kn = k0 + 8;
        if (kn < K) {
            if (MODE == 1) {
                aPf = *reinterpret_cast<const float4*>(
                    &A_or_x[(size_t)blockIdx.y * Hh * Bz + (size_t)(kn + arow) * Bz + acol]);
            } else {
                int m = m0 + lrow;
                int tt = m >> 7, b = m & 127;
#pragma unroll
                for (int i = 0; i < 4; i++)
                    aPfS[i] = A_or_x[(size_t)b * (INZ * Tt) + (size_t)(kn + lkq + i) * Tt + tt];
            }
            bPf = *reinterpret_cast<const float4*>(&W[(size_t)(n0 + lrow) * K + kn + lkq]);
        }

#pragma unroll
        for (int kk = 0; kk < 8; kk++) {
            float a[8];
            *reinterpret_cast<float4*>(&a[0]) = *reinterpret_cast<const float4*>(&As[kk][tyy * 8]);
            *reinterpret_cast<float4*>(&a[4]) = *reinterpret_cast<const float4*>(&As[kk][tyy * 8 + 4]);
            ulonglong2 bp01 = *reinterpret_cast<const ulonglong2*>(&Bs[kk][txx * 8]);
            ulonglong2 bp23 = *reinterpret_cast<const ulonglong2*>(&Bs[kk][txx * 8 + 4]);
            u64 bp[4] = {bp01.x, bp01.y, bp23.x, bp23.y};
#pragma unroll
            for (int i = 0; i < 8; i++) {
                u64 as = pack2(a[i], a[i]);
#pragma unroll
                for (int j = 0; j < 4; j++)
                    acc[i][j] = fma2(as, bp[j], acc[i][j]);
            }
        }
        __syncthreads();
    }

#pragma unroll
    for (int i = 0; i < 8; i++) {
        int m = m0 + tyy * 8 + i;
#pragma unroll
        for (int j = 0; j < 4; j++) {
            int n = n0 + txx * 8 + 2 * j;
            float lo, hi; unpack2(acc[i][j], lo, hi);
            float2 v = make_float2(lo + b0v[n] + b1v[n], hi + b0v[n + 1] + b1v[n + 1]);
            *reinterpret_cast<float2*>(&out[(size_t)m * G4 + n]) = v;
        }
    }
}

// ---------------- persistent LSTM, 1 B/FMA + dataflow chunk sync ----------------
// 128 blocks x 512 threads (16 warps). Block owns 4 hidx x 4 gates. Chunk c of
// h (k-rows 128c..) is produced by blocks [32c,32c+32); counter ck[c] >= 32*t
// means version consumable at step t is published (h^t lives in hs_t[t-1], or
// h0buf for t=0). Only tid0 polls counters; all other sync is __syncthreads.
// Inner loop: 4 LDS.128 + 8 pack2 + 32 FFMA2 per kk (1 B/FMA on the crossbar).
// Reduction via smem dump (reusing the h-chunk buffer) + fully parallel
// epilogue; c-state per-thread in registers; h stored ONCE (into hs_t ring).
__global__ void __launch_bounds__(512, 1)
lstm_persistent(const float* __restrict__ xp_all,   // [t][b][2048]
                const float* __restrict__ whh,      // [2048][512]
                const float* __restrict__ c0,       // [b][512]
                const float* __restrict__ h0buf,    // [512][128] initial h
                float* __restrict__ hs_t,           // [t][512][128] ring + output
                int layer) {
    extern __shared__ char sm_[];
    float* ws    = (float*)sm_;                    // [512][16]  32KB
    float* hb    = (float*)(sm_ + 32768);          // [2][128][128] 128KB (reused as red)
    u64*   red64 = (u64*)(sm_ + 32768);            // [16][1056] u64 = 132KB
    float* xs    = (float*)(sm_ + 32768 + 135168); // [128][20] 10KB

    const int tid  = threadIdx.x;
    const int lane = tid & 31;
    const int wrp  = tid >> 5;        // 0..15 : k-slice
    const int rh   = lane >> 4;       // 0/1 : hh half
    const int bo   = lane & 15;       // b-octet
    const int hidx0 = blockIdx.x * 4;
    const int myGrp = blockIdx.x >> 5;

    // epilogue identity: thread t <-> (b = t&127, hh = t>>7)
    const int eb  = tid & 127;
    const int ehh = tid >> 7;
    const int erh = ehh >> 1, ehp = ehh & 1;
    const int ebo = eb >> 3,  ej  = eb & 7;
    const int lane_src = erh * 16 + ebo;
    const int idx0 = ej * 4 + ehp * 2;

    unsigned* ck = &g_ck[layer * 4];

    // weights: ws[k*16 + hh*4 + q], coalesced over k
    for (int r = tid; r < 8192; r += 512) {
        int k = r & 511, idx = r >> 9;
        int hh = idx >> 2, q = idx & 3;
        ws[k * 16 + idx] = whh[(size_t)(q * Hh + hidx0 + hh) * Hh + k];
    }
    // c-state: 1 per thread
    float creg = c0[(size_t)eb * Hh + hidx0 + ehh];

    const unsigned hb_s = (unsigned)__cvta_generic_to_shared(hb);

    // xp prefetch for t=0: thread stages float4 for (b = tid>>2, q = tid&3)
    float4 xr = *reinterpret_cast<const float4*>(
        &xp_all[(size_t)(tid >> 2) * G4 + (tid & 3) * Hh + hidx0]);

    __syncthreads();

    for (int t = 0; t < Tt; t++) {
        const float* hp = (t == 0) ? h0buf : (hs_t + (size_t)(t - 1) * Hh * Bz);

        // gate on chunk 0 of version t, then issue it into slot 0
        if (tid == 0 && t > 0) {
            unsigned target = (unsigned)(32 * t);
            while (ld_acq(&ck[0]) < target) {}
        }
        __syncthreads();
        {
            unsigned sa = hb_s + tid * 16;
            const char* gp = (const char*)hp + tid * 16;
#pragma unroll
            for (int i = 0; i < 8; i++)
                asm volatile("cp.async.cg.shared.global [%0], [%1], 16;"
                             :: "r"(sa + i * 8192), "l"(gp + i * 8192));
            asm volatile("cp.async.commit_group;" ::: "memory");
        }

        u64 acc[8][4];
#pragma unroll
        for (int j = 0; j < 8; j++)
#pragma unroll
            for (int p = 0; p < 4; p++) acc[j][p] = 0ull;

#pragma unroll
        for (int c = 0; c < 4; c++) {
            asm volatile("cp.async.wait_group 0;" ::: "memory");
            if (tid == 0 && c < 3 && t > 0) {
                unsigned target = (unsigned)(32 * t);
                while (ld_acq(&ck[c + 1]) < target) {}
            }
            __syncthreads();

            if (c < 3) {
                unsigned sa = hb_s + ((c + 1) & 1) * 65536 + tid * 16;
                const char* gp = (const char*)(hp + (c + 1) * 16384) + tid * 16;
#pragma unroll
                for (int i = 0; i < 8; i++)
                    asm volatile("cp.async.cg.shared.global [%0], [%1], 16;"
                                 :: "r"(sa + i * 8192), "l"(gp + i * 8192));
                asm volatile("cp.async.commit_group;" ::: "memory");
            }

            const float* bufk = hb + (c & 1) * 16384 + (size_t)(wrp * 8) * 128 + bo * 8;
            const float* wsk  = ws + (size_t)(c * 128 + wrp * 8) * 16 + rh * 8;
#pragma unroll
            for (int kk = 0; kk < 8; kk++) {
                float4 h0 = *reinterpret_cast<const float4*>(bufk + (size_t)kk * 128);
                float4 h1 = *reinterpret_cast<const float4*>(bufk + (size_t)kk * 128 + 4);
                ulonglong2 wa = *reinterpret_cast<const ulonglong2*>(wsk + (size_t)kk * 16);
                ulonglong2 wb = *reinterpret_cast<const ulonglong2*>(wsk + (size_t)kk * 16 + 4);
                float hv[8] = {h0.x, h0.y, h0.z, h0.w, h1.x, h1.y, h1.z, h1.w};
#pragma unroll
                for (int j = 0; j < 8; j++) {
                    u64 hs = pack2(hv[j], hv[j]);
                    acc[j][0] = fma2(hs, wa.x, acc[j][0]);
                    acc[j][1] = fma2(hs, wa.y, acc[j][1]);
                    acc[j][2] = fma2(hs, wb.x, acc[j][2]);
                    acc[j][3] = fma2(hs, wb.y, acc[j][3]);
                }
            }
        }

        __syncthreads();   // all chunks consumed; hb free for reduction

        // stage xp tile (padded stride 20 floats per b)
        *reinterpret_cast<float4*>(&xs[(tid >> 2) * 20 + (tid & 3) * 4]) = xr;

        // dump partials: warp wrp, lane -> red64[wrp*1056 + lane*33 + j*4 + p]
        {
            u64* rp = red64 + (size_t)wrp * 1056 + (size_t)lane * 33;
#pragma unroll
            for (int j = 0; j < 8; j++)
#pragma unroll
                for (int p = 0; p < 4; p++) rp[j * 4 + p] = acc[j][p];
        }
        __syncthreads();

        // per-thread: sum 16 k-slice partials for cell (eb, ehh)
        u64 s0 = 0ull, s1 = 0ull;
        {
            const u64* rp = red64 + (size_t)lane_src * 33 + idx0;
#pragma unroll
            for (int g = 0; g < 16; g++) {
                s0 = add2(s0, rp[(size_t)g * 1056]);
                s1 = add2(s1, rp[(size_t)g * 1056 + 1]);
            }
        }

        // epilogue (gate order i,f,g,o); single h store into the hs_t ring
        {
            float gi_, gf_, gg_, go_;
            unpack2(s0, gi_, gf_);
            unpack2(s1, gg_, go_);
            const float* xb = xs + eb * 20 + ehh;
            float gi = gi_ + xb[0];
            float gf = gf_ + xb[4];
            float gg = gg_ + xb[8];
            float go = go_ + xb[12];
            float cc = fsig(gf) * creg + fsig(gi) * ftanh_(gg);
            creg = cc;
            float h = fsig(go) * ftanh_(cc);
            hs_t[(size_t)t * Hh * Bz + (hidx0 + ehh) * Bz + eb] = h;
        }

        // prefetch next step's xp (independent of h)
        if (t + 1 < Tt)
            xr = *reinterpret_cast<const float4*>(
                &xp_all[(size_t)(t + 1) * Bz * G4 +
                        (size_t)(tid >> 2) * G4 + (tid & 3) * Hh + hidx0]);

        // publish this block's h slice
        __syncthreads();
        if (tid == 0) red_rel_add(&ck[myGrp], 1u);
    }
}

// ---------------- encoder output transpose: out[b][h][t] = hse_t[t][h][b] ----------------
__global__ void __launch_bounds__(256)
enc_transpose(const float* __restrict__ hs_t, float* __restrict__ out) {
    __shared__ float tile[32][33];
    int t0 = blockIdx.x * 32, b0 = blockIdx.y * 32, h = blockIdx.z;
    int tx = threadIdx.x & 31, ty = threadIdx.x >> 5;
#pragma unroll
    for (int i = ty; i < 32; i += 8)
        tile[i][tx] = hs_t[(size_t)(t0 + i) * (Hh * Bz) + (size_t)h * Bz + b0 + tx];
    __syncthreads();
#pragma unroll
    for (int i = ty; i < 32; i += 8)
        out[(size_t)(b0 + i) * (Hh * Tt) + (size_t)h * Tt + t0 + tx] = tile[tx][i];
}

// ---------------- FC partial GEMM (f32x2, k-split over t) ----------------
__global__ void __launch_bounds__(256)
fc_partial(const float* __restrict__ hsd_t, const float* __restrict__ Wfc) {
    const int t  = blockIdx.y;
    const int o0 = blockIdx.x * 128;
    const int tid = threadIdx.x;
    const int txx = tid & 15;
    const int tyy = tid >> 4;
    const int lrow = tid >> 1;
    const int lkq  = (tid & 1) * 4;
    const int arow = tid >> 5;
    const int acol = (tid & 31) * 4;

    __shared__ __align__(16) float As[8][128];
    __shared__ __align__(16) float Bs[8][128];

    u64 acc[8][4];
#pragma unroll
    for (int i = 0; i < 8; i++)
#pragma unroll
        for (int j = 0; j < 4; j++) acc[i][j] = 0ull;

    const float* Abase = hsd_t + (size_t)t * (Hh * Bz);

    for (int h0 = 0; h0 < Hh; h0 += 8) {
        *reinterpret_cast<float4*>(&As[arow][acol]) =
            *reinterpret_cast<const float4*>(&Abase[(size_t)(h0 + arow) * Bz + acol]);
#pragma unroll
        for (int i = 0; i < 4; i++)
            Bs[lkq + i][lrow] = Wfc[(size_t)(o0 + lrow) * (Hh * Tt) + (size_t)(h0 + lkq + i) * Tt + t];
        __syncthreads();
#pragma unroll
        for (int kk = 0; kk < 8; kk++) {
            float a[8];
            *reinterpret_cast<float4*>(&a[0]) = *reinterpret_cast<const float4*>(&As[kk][tyy * 8]);
            *reinterpret_cast<float4*>(&a[4]) = *reinterpret_cast<const float4*>(&As[kk][tyy * 8 + 4]);
            ulonglong2 bp01 = *reinterpret_cast<const ulonglong2*>(&Bs[kk][txx * 8]);
            ulonglong2 bp23 = *reinterpret_cast<const ulonglong2*>(&Bs[kk][txx * 8 + 4]);
            u64 bp[4] = {bp01.x, bp01.y, bp23.x, bp23.y};
#pragma unroll
            for (int i = 0; i < 8; i++) {
                u64 as = pack2(a[i], a[i]);
#pragma unroll
                for (int j = 0; j < 4; j++)
                    acc[i][j] = fma2(as, bp[j], acc[i][j]);
            }
        }
        __syncthreads();
    }

    float* part = g_fcp + (size_t)t * (Bz * OUTL);
#pragma unroll
    for (int i = 0; i < 8; i++) {
        int b = tyy * 8 + i;
#pragma unroll
        for (int j = 0; j < 4; j++) {
            float lo, hi; unpack2(acc[i][j], lo, hi);
            *reinterpret_cast<float2*>(&part[(size_t)b * OUTL + o0 + txx * 8 + 2 * j]) =
                make_float2(lo, hi);
        }
    }
}

__global__ void fc_reduce(const float* __restrict__ bfc, float* __restrict__ decoded) {
    int i = blockIdx.x * blockDim.x + threadIdx.x;
    if (i >= Bz * OUTL) return;
    float s = bfc[i & (OUTL - 1)];
    for (int t = 0; t < Tt; t++) s += g_fcp[(size_t)t * (Bz * OUTL) + i];
    decoded[i] = s;
}

// ---------------- launch ----------------
extern "C" void kernel_launch(void* const* d_in, const int* in_sizes, int n_in,
                              void* d_out, int out_size) {
    const float* x     = (const float*)d_in[0];
    const float* h0e   = (const float*)d_in[1];
    const float* c0e   = (const float*)d_in[2];
    const float* Wih_e = (const float*)d_in[3];
    const float* Whh_e = (const float*)d_in[4];
    const float* bih_e = (const float*)d_in[5];
    const float* bhh_e = (const float*)d_in[6];
    const float* h0d   = (const float*)d_in[7];
    const float* c0d   = (const float*)d_in[8];
    const float* Wih_d = (const float*)d_in[9];
    const float* Whh_d = (const float*)d_in[10];
    const float* bih_d = (const float*)d_in[11];
    const float* bhh_d = (const float*)d_in[12];
    const float* Wfc   = (const float*)d_in[13];
    const float* bfc   = (const float*)d_in[14];

    float* out = (float*)d_out;
    float* enc_out = out;
    float* decoded = out + (size_t)Bz * Hh * Tt;

    float *xpe, *xpd, *hse, *hsd, *hA, *h2A;
    cudaGetSymbolAddress((void**)&xpe, g_xpe);
    cudaGetSymbolAddress((void**)&xpd, g_xpd);
    cudaGetSymbolAddress((void**)&hse, g_hse);
    cudaGetSymbolAddress((void**)&hsd, g_hsd);
    cudaGetSymbolAddress((void**)&hA,  g_hA);
    cudaGetSymbolAddress((void**)&h2A, g_h2A);

    const int SMEM = 32768 + 135168 + 10240;   // 178176
    cudaFuncSetAttribute(lstm_persistent, cudaFuncAttributeMaxDynamicSharedMemorySize, SMEM);

    init_h<<<(Hh * Bz + 255) / 256, 256>>>(h0e, h0d);
    init_bar<<<1, 32>>>();

    inproj_gemm<0><<<dim3(16, 256), 256>>>(x, Wih_e, bih_e, bhh_e, xpe, INZ);

    lstm_persistent<<<NBLK, 512, SMEM>>>(xpe, Whh_e, c0e, hA, hse, 0);

    inproj_gemm<1><<<dim3(16, 256), 256>>>(hse, Wih_d, bih_d, bhh_d, xpd, Hh);

    lstm_persistent<<<NBLK, 512, SMEM>>>(xpd, Whh_d, c0d, h2A, hsd, 1);

    enc_transpose<<<dim3(Tt / 32, Bz / 32, Hh), 256>>>(hse, enc_out);

    fc_partial<<<dim3(4, Tt), 256>>>(hsd, Wfc);
    fc_reduce<<<(Bz * OUTL + 255) / 256, 256>>>(bfc, decoded);
}